// round 10
// baseline (speedup 1.0000x reference)
#include <cuda_runtime.h>

#define B 128
#define K 17
#define HW 9216          // 96*96
#define NVEC (HW/4)      // 2304
#define TOPK 8
#define THREADS1 256
#define NBLOCKS (B * K)  // 2176 producer blocks; block 2176 = consumer

__device__ float g_per_joint[B * K];
__device__ unsigned int g_flag[B * K];   // zero-init; reset by consumer

__global__ void __launch_bounds__(THREADS1, 4)
mse_ohkm_flag_kernel(const float* __restrict__ pred,
                     const float* __restrict__ gt,
                     const float* __restrict__ tw,
                     float* __restrict__ out) {
    const int tid  = threadIdx.x;
    const int lane = tid & 31;
    const int wid  = tid >> 5;

    if (blockIdx.x == NBLOCKS) {
        // ---------------- consumer block (last wave) ----------------
        __shared__ float sh[B];
        if (tid < B) {
            float t[TOPK];
            #pragma unroll
            for (int j = 0; j < TOPK; j++) t[j] = -3.4e38f;

            #pragma unroll 1
            for (int i = 0; i < K; i++) {
                const int idx = tid * K + i;
                unsigned int f;
                // spin until producer's release-store lands
                do {
                    asm volatile("ld.acquire.gpu.global.u32 %0, [%1];"
                                 : "=r"(f) : "l"(&g_flag[idx]) : "memory");
                    if (!f) __nanosleep(64);
                } while (!f);
                float x = g_per_joint[idx];   // ordered by the acquire above
                #pragma unroll
                for (int j = 0; j < TOPK; j++) {
                    float o = t[j];
                    bool gtp = x > o;
                    t[j] = gtp ? x : o;
                    x    = gtp ? o : x;
                }
            }
            float s = 0.0f;
            #pragma unroll
            for (int j = 0; j < TOPK; j++) s += t[j];
            sh[tid] = s;

            // reset this sample's flags for the next graph replay
            #pragma unroll 1
            for (int i = 0; i < K; i++)
                g_flag[tid * K + i] = 0u;
        }
        __syncthreads();
        #pragma unroll
        for (int stride = B / 2; stride > 0; stride >>= 1) {
            if (tid < stride) sh[tid] += sh[tid + stride];
            __syncthreads();
        }
        if (tid == 0)
            out[0] = sh[0] * (1.0f / (float)(B * TOPK));
        return;
    }

    // ---------------- producer blocks: pure streaming ----------------
    const int bk = blockIdx.x;
    const float4* __restrict__ p = reinterpret_cast<const float4*>(pred + (size_t)bk * HW);
    const float4* __restrict__ g = reinterpret_cast<const float4*>(gt   + (size_t)bk * HW);

    float acc = 0.0f;
    #pragma unroll
    for (int j = 0; j < NVEC / THREADS1; j++) {   // 9 iterations
        const int i = tid + j * THREADS1;
        float4 a = p[i];
        float4 b = g[i];
        float d0 = a.x - b.x;
        float d1 = a.y - b.y;
        float d2 = a.z - b.z;
        float d3 = a.w - b.w;
        acc += d0 * d0 + d1 * d1 + d2 * d2 + d3 * d3;
    }

    #pragma unroll
    for (int off = 16; off > 0; off >>= 1)
        acc += __shfl_down_sync(0xFFFFFFFFu, acc, off);

    __shared__ float warp_sums[THREADS1 / 32];
    if (lane == 0) warp_sums[wid] = acc;
    __syncthreads();

    if (wid == 0) {
        float v = (lane < THREADS1 / 32) ? warp_sums[lane] : 0.0f;
        #pragma unroll
        for (int off = 4; off > 0; off >>= 1)
            v += __shfl_down_sync(0xFFFFFFFFu, v, off);
        if (lane == 0) {
            const float w = tw[bk];
            g_per_joint[bk] = v * w * w * (1.0f / (float)HW);
            // fire-and-forget release store: value above is visible
            // before flag; no round-trip, block retires immediately
            asm volatile("st.global.release.gpu.u32 [%0], %1;"
                         :: "l"(&g_flag[bk]), "r"(1u) : "memory");
        }
    }
}

extern "C" void kernel_launch(void* const* d_in, const int* in_sizes, int n_in,
                              void* d_out, int out_size) {
    const float* pred = (const float*)d_in[0];   // output [B,K,H,W]
    const float* gt   = (const float*)d_in[1];   // target [B,K,H,W]
    const float* tw   = (const float*)d_in[2];   // target_weight [B,K,1]
    float* out = (float*)d_out;

    mse_ohkm_flag_kernel<<<NBLOCKS + 1, THREADS1>>>(pred, gt, tw, out);
}

// round 11
// speedup vs baseline: 1.2839x; 1.2839x over previous
#include <cuda_runtime.h>

#define B 128
#define K 17
#define HW 9216            // 96*96
#define NVEC (HW/4)        // 2304 float4 per joint
#define TOPK 8
#define THREADS 1024
#define NW (THREADS/32)    // 32 warps

__device__ float g_per_sample[B];
__device__ unsigned int g_counter = 0;

__global__ void __launch_bounds__(THREADS, 1)
mse_ohkm_sample_kernel(const float* __restrict__ pred,
                       const float* __restrict__ gt,
                       const float* __restrict__ tw,
                       float* __restrict__ out) {
    const int b    = blockIdx.x;       // one block per sample
    const int tid  = threadIdx.x;
    const int lane = tid & 31;
    const int wid  = tid >> 5;

    __shared__ float wsum[K][NW];      // per-joint per-warp partials
    __shared__ float jsum[K];          // per-joint MSE

    const float4* __restrict__ pb =
        reinterpret_cast<const float4*>(pred + (size_t)b * K * HW);
    const float4* __restrict__ gb =
        reinterpret_cast<const float4*>(gt   + (size_t)b * K * HW);

    // ---- streaming: 17 joints, NO block barriers in this loop ----
    #pragma unroll 2
    for (int j = 0; j < K; j++) {
        const float4* __restrict__ p = pb + j * NVEC;
        const float4* __restrict__ g = gb + j * NVEC;

        // 2304 vecs / 1024 threads: 2 each + first 256 threads take a 3rd
        float4 a0 = p[tid];        float4 c0 = g[tid];
        float4 a1 = p[tid + 1024]; float4 c1 = g[tid + 1024];

        float d0 = a0.x - c0.x, d1 = a0.y - c0.y,
              d2 = a0.z - c0.z, d3 = a0.w - c0.w;
        float acc = d0 * d0 + d1 * d1 + d2 * d2 + d3 * d3;
        d0 = a1.x - c1.x; d1 = a1.y - c1.y;
        d2 = a1.z - c1.z; d3 = a1.w - c1.w;
        acc += d0 * d0 + d1 * d1 + d2 * d2 + d3 * d3;

        if (tid < NVEC - 2048) {       // 256 threads
            float4 a2 = p[tid + 2048]; float4 c2 = g[tid + 2048];
            d0 = a2.x - c2.x; d1 = a2.y - c2.y;
            d2 = a2.z - c2.z; d3 = a2.w - c2.w;
            acc += d0 * d0 + d1 * d1 + d2 * d2 + d3 * d3;
        }

        #pragma unroll
        for (int off = 16; off > 0; off >>= 1)
            acc += __shfl_down_sync(0xFFFFFFFFu, acc, off);
        if (lane == 0) wsum[j][wid] = acc;   // private slot, no sync needed
    }
    __syncthreads();   // the ONLY block barrier before the tail

    // ---- per-joint cross-warp reduce: warp w (<17) owns joint w ----
    if (wid < K) {
        float v = wsum[wid][lane];
        #pragma unroll
        for (int off = 16; off > 0; off >>= 1)
            v += __shfl_down_sync(0xFFFFFFFFu, v, off);
        if (lane == 0) {
            const float w = tw[b * K + wid];
            jsum[wid] = v * w * w * (1.0f / (float)HW);
        }
    }
    __syncthreads();

    // ---- block-local OHKM top-8 + per-sample store (thread 0) ----
    if (tid == 0) {
        float t[TOPK];
        #pragma unroll
        for (int j = 0; j < TOPK; j++) t[j] = -3.4e38f;
        #pragma unroll
        for (int i = 0; i < K; i++) {
            float x = jsum[i];
            #pragma unroll
            for (int j = 0; j < TOPK; j++) {
                float o = t[j];
                bool gtp = x > o;
                t[j] = gtp ? x : o;
                x    = gtp ? o : x;
            }
        }
        float s = 0.0f;
        #pragma unroll
        for (int j = 0; j < TOPK; j++) s += t[j];
        g_per_sample[b] = s;

        // one release-atomic per 25us block: negligible amortized cost
        unsigned int old;
        asm volatile("atom.add.release.gpu.global.u32 %0, [%1], 1;"
                     : "=r"(old) : "l"(&g_counter) : "memory");
        if (old == (unsigned int)(B - 1)) {
            asm volatile("fence.acq_rel.gpu;" ::: "memory");
            float tot = 0.0f;
            #pragma unroll
            for (int i = 0; i < B; i++)
                tot += __ldcg(&g_per_sample[i]);   // L2-hot, MLP-overlapped
            out[0] = tot * (1.0f / (float)(B * TOPK));
            g_counter = 0u;   // reset for next graph replay
        }
    }
}

extern "C" void kernel_launch(void* const* d_in, const int* in_sizes, int n_in,
                              void* d_out, int out_size) {
    const float* pred = (const float*)d_in[0];   // output [B,K,H,W]
    const float* gt   = (const float*)d_in[1];   // target [B,K,H,W]
    const float* tw   = (const float*)d_in[2];   // target_weight [B,K,1]
    float* out = (float*)d_out;

    mse_ohkm_sample_kernel<<<B, THREADS>>>(pred, gt, tw, out);
}